// round 5
// baseline (speedup 1.0000x reference)
#include <cuda_runtime.h>

#define T_  512
#define I_  15
#define H_  64
#define RPB 4                 // batch rows per block (shared by all 4 warps)
#define THREADS 128
#define NBLOCKS (4096 / RPB)  // 1024

typedef unsigned long long ull;

// packed fp32x2 FMA (sm_100+): d.lo += a.lo*b.lo; d.hi += a.hi*b.hi
__device__ __forceinline__ void ffma2(ull &d, ull a, ull b) {
    asm("fma.rn.f32x2 %0, %1, %2, %0;" : "+l"(d) : "l"(a), "l"(b));
}
__device__ __forceinline__ ull pack2(float a, float b) {
    ull r; asm("mov.b64 %0, {%1, %2};" : "=l"(r) : "f"(a), "f"(b)); return r;
}
__device__ __forceinline__ float2 unpack2(ull v) {
    float2 f; asm("mov.b64 {%0, %1}, %2;" : "=f"(f.x), "=f"(f.y) : "l"(v)); return f;
}
// Accurate tanh, 2 MUFU: tanh(x) = (e-1)/(e+1), e = 2^(x*2*log2(e))
__device__ __forceinline__ float fast_tanh(float x) {
    float e; asm("ex2.approx.f32 %0, %1;" : "=f"(e) : "f"(x * 2.8853900817779268f));
    float r; asm("rcp.approx.f32 %0, %1;" : "=f"(r) : "f"(e + 1.0f));
    return (e - 1.0f) * r;
}

// Permuted h-row layout (64 floats): h[k], k = 16*kq + 4*c + e  lives at
// float offset c*16 + kq*4 + e.  Lane with quarter u reads chunk (r,c) at
// byte r*256 + c*64 + u*16: 4 distinct 16B chunks in one 64B span -> disjoint
// banks, 8-lane broadcast each => 1 wavefront per LDS.128.
// x rows are plain 16 floats (15 real + zero pad); lane u reads floats 4u..4u+3.

__global__ void __launch_bounds__(THREADS, 7) rnn_fused_kernel(
    const float* __restrict__ x,     // [B, T, I]
    const float* __restrict__ W_ih,  // [H, I]
    const float* __restrict__ W_hh,  // [H, H]
    const float* __restrict__ b_ih,  // [H]
    const float* __restrict__ b_hh,  // [H]
    const float* __restrict__ fc_w,  // [1, H]
    const float* __restrict__ fc_b,  // [1]
    float* __restrict__ out)         // [B, 1]
{
    __shared__ __align__(16) float hbuf[2][RPB][H_];  // ping-pong h (permuted)
    __shared__ __align__(16) float xbuf[2][RPB][16];  // staged x_t (+pad 0)

    const int tid  = threadIdx.x;
    const int wid  = tid >> 5;
    const int lane = tid & 31;
    const int u    = lane & 3;              // k-quarter: k in [16u, 16u+16)
    const int tm   = wid * 8 + (lane >> 2); // team id 0..31
    const int j0   = tm, j1 = tm + 32;      // this team's two outputs
    const int myj  = (u & 1) ? j1 : j0;     // j this lane finalizes (u<2 stores)
    const int row0 = blockIdx.x * RPB;

    // ---- Weights to registers (quarter of k per lane) ----
    ull whhA[8], whhB[8];    // W_hh[j][16u .. 16u+16)
    {
        const ull* wa = (const ull*)(W_hh + j0 * H_ + u * 16);
        const ull* wb = (const ull*)(W_hh + j1 * H_ + u * 16);
        #pragma unroll
        for (int i = 0; i < 8; ++i) { whhA[i] = wa[i]; whhB[i] = wb[i]; }
    }
    ull wihA[2], wihB[2];    // W_ih[j][4u .. 4u+4) (pad idx 15 -> 0)
    #pragma unroll
    for (int s = 0; s < 2; ++s) {
        int i0 = u * 4 + 2 * s;
        float a0 = W_ih[j0 * I_ + i0];
        float b0 = (i0 + 1 < I_) ? W_ih[j0 * I_ + i0 + 1] : 0.0f;
        float a1 = W_ih[j1 * I_ + i0];
        float b1 = (i0 + 1 < I_) ? W_ih[j1 * I_ + i0 + 1] : 0.0f;
        wihA[s] = pack2(a0, b0);
        wihB[s] = pack2(a1, b1);
    }
    const float bias = b_ih[myj] + b_hh[myj];
    // store slot of h[myj] in the permuted row
    const int hoff = ((myj >> 2) & 3) * 16 + (myj >> 4) * 4 + (myj & 3);

    // ---- Init: h0 = 0, stage x(t=0), zero x pads ----
    #pragma unroll
    for (int i = 0; i < (RPB * H_) / THREADS; ++i)
        ((float*)hbuf[0])[tid + i * THREADS] = 0.0f;
    const int  sr = tid / 15, si = tid % 15;     // staging lanes 0..59
    const bool stg = (tid < 60);
    const float* xp = x + ((long)(row0 + sr) * T_) * I_ + si;
    if (stg) xbuf[0][sr][si] = *xp;
    if (tid < RPB) { xbuf[0][tid][15] = 0.0f; xbuf[1][tid][15] = 0.0f; }
    xp += I_;
    __syncthreads();

    // ---- Recurrence ----
    for (int t = 0; t < T_; ++t) {
        const int cur = t & 1, nxt = cur ^ 1;

        // prefetch x for t+1 (hidden behind this step's math)
        float xn = 0.0f;
        const bool pf = stg && (t + 1 < T_);
        if (pf) { xn = __ldg(xp); xp += I_; }

        const ulonglong2* hb2 = (const ulonglong2*)hbuf[cur] + u; // lane chunks
        const ulonglong2* xb2 = (const ulonglong2*)xbuf[cur] + u;

        #pragma unroll
        for (int r = 0; r < RPB; ++r) {
            ull a0 = 0ULL, a1 = 0ULL;
            // input projection: 1 LDS.128 (this lane's 4 inputs)
            ulonglong2 vx = xb2[r * 4];
            ffma2(a0, vx.x, wihA[0]); ffma2(a0, vx.y, wihA[1]);
            ffma2(a1, vx.x, wihB[0]); ffma2(a1, vx.y, wihB[1]);
            // recurrent quarter: 4 LDS.128, 4 ffma2 each
            #pragma unroll
            for (int c = 0; c < 4; ++c) {
                ulonglong2 vh = hb2[r * 16 + c * 4];
                ffma2(a0, vh.x, whhA[2 * c]); ffma2(a0, vh.y, whhA[2 * c + 1]);
                ffma2(a1, vh.x, whhB[2 * c]); ffma2(a1, vh.y, whhB[2 * c + 1]);
            }
            // 4-lane team reduce for both outputs in 2 shfls
            float2 f0 = unpack2(a0), f1 = unpack2(a1);
            float s0 = f0.x + f0.y;          // partial for j0, my quarter
            float s1 = f1.x + f1.y;          // partial for j1, my quarter
            float send = (u & 1) ? s0 : s1;
            float keep = (u & 1) ? s1 : s0;
            float a = keep + __shfl_xor_sync(0xffffffffu, send, 1);
            float b = a + __shfl_xor_sync(0xffffffffu, a, 2);
            float hnew = fast_tanh(b + bias);
            if (u < 2) hbuf[nxt][r][hoff] = hnew;   // u=0 -> j0, u=1 -> j1
        }
        if (pf) xbuf[nxt][sr][si] = xn;
        __syncthreads();
    }

    // ---- Head: out[row] = sum_k h_T[row][k] * fc_w[k] + fc_b ----
    // Final h lives in hbuf[0] (T even). Warp 0 alone does the tiny head.
    if (wid == 0) {
        const ull* fwp = (const ull*)(fc_w + u * 16);   // my quarter of fc_w
        const ulonglong2* hb2 = (const ulonglong2*)hbuf[0] + u;
        float res[RPB];
        #pragma unroll
        for (int r = 0; r < RPB; ++r) {
            ull facc = 0ULL;
            #pragma unroll
            for (int c = 0; c < 4; ++c) {
                ulonglong2 vh = hb2[r * 16 + c * 4];
                ffma2(facc, vh.x, fwp[2 * c]); ffma2(facc, vh.y, fwp[2 * c + 1]);
            }
            float2 f = unpack2(facc);
            float s = (lane < 4) ? (f.x + f.y) : 0.0f;  // teams>0 are duplicates
            #pragma unroll
            for (int o = 1; o <= 16; o <<= 1)
                s += __shfl_xor_sync(0xffffffffu, s, o);
            res[r] = s;
        }
        if (lane == 0) {
            float fb = fc_b[0];
            #pragma unroll
            for (int r = 0; r < RPB; ++r) out[row0 + r] = res[r] + fb;
        }
    }
}

extern "C" void kernel_launch(void* const* d_in, const int* in_sizes, int n_in,
                              void* d_out, int out_size) {
    const float* x    = (const float*)d_in[0];
    const float* W_ih = (const float*)d_in[1];
    const float* W_hh = (const float*)d_in[2];
    const float* b_ih = (const float*)d_in[3];
    const float* b_hh = (const float*)d_in[4];
    const float* fc_w = (const float*)d_in[5];
    const float* fc_b = (const float*)d_in[6];
    rnn_fused_kernel<<<NBLOCKS, THREADS>>>(x, W_ih, W_hh, b_ih, b_hh,
                                           fc_w, fc_b, (float*)d_out);
}